// round 2
// baseline (speedup 1.0000x reference)
#include <cuda_runtime.h>

#define NN 20000
#define NE 320000
#define LDIM 128
#define TILE 64
#define NT 256
#define NLAYERS 5

// -------- scratch (static device allocations; no runtime alloc) --------
__device__ float g_h[NN * LDIM];     // node features
__device__ float g_P[NN * LDIM];     // h @ W1a  (dst-side precontraction)
__device__ float g_Q[NN * LDIM];     // h @ W1b  (src-side precontraction)
__device__ float g_agg[NN * LDIM];   // segment sum accumulator
__device__ float g_e[NE * LDIM];     // encoded edge features (constant over layers)

typedef unsigned long long u64t;

// -------- packed fp32x2 primitives --------
__device__ __forceinline__ void ffma2(u64t& d, u64t a, u64t b) {
    asm("fma.rn.f32x2 %0, %1, %2, %0;" : "+l"(d) : "l"(a), "l"(b));
}
__device__ __forceinline__ u64t pack2(float x, float y) {
    u64t v; asm("mov.b64 %0, {%1, %2};" : "=l"(v) : "f"(x), "f"(y)); return v;
}
__device__ __forceinline__ float2 unpack2(u64t v) {
    float2 f; asm("mov.b64 {%0, %1}, %2;" : "=f"(f.x), "=f"(f.y) : "l"(v)); return f;
}

// -------- helpers --------
__device__ __forceinline__ void cp_f4(float* dst, const float* __restrict__ src,
                                      int n, int tid) {
    for (int i = tid * 4; i < n; i += NT * 4)
        *(float4*)(dst + i) = *(const float4*)(src + i);
}

// copy n floats (contiguous) into DUPLICATED layout: dst[2j]=dst[2j+1]=src[j]
__device__ __forceinline__ void cp_dup(float* dst, const float* __restrict__ src,
                                       int n, int tid) {
    for (int i = tid * 4; i < n; i += NT * 4) {
        float4 v = *(const float4*)(src + i);
        float4 d0 = make_float4(v.x, v.x, v.y, v.y);
        float4 d1 = make_float4(v.z, v.z, v.w, v.w);
        *(float4*)(dst + 2 * i)     = d0;
        *(float4*)(dst + 2 * i + 4) = d1;
    }
}

// gather 64x128 row tile from [nrows,128] (clamped) into DUPLICATED layout
__device__ __forceinline__ void load_tile_rows_dup(float* Ad, const float* __restrict__ src,
                                                   int r0, int nrows, int tid) {
    for (int i = tid * 4; i < TILE * LDIM; i += NT * 4) {
        int r = i >> 7;
        int k = i & (LDIM - 1);
        int gr = r0 + r;
        if (gr >= nrows) gr = nrows - 1;
        float4 v = *(const float4*)(src + (size_t)gr * LDIM + k);
        *(float4*)(Ad + 2 * i)     = make_float4(v.x, v.x, v.y, v.y);
        *(float4*)(Ad + 2 * i + 4) = make_float4(v.z, v.z, v.w, v.w);
    }
}

__device__ __forceinline__ void red_add_v4(float* addr, float4 v) {
    asm volatile("red.global.add.v4.f32 [%0], {%1,%2,%3,%4};"
                 :: "l"(addr), "f"(v.x), "f"(v.y), "f"(v.z), "f"(v.w)
                 : "memory");
}

__device__ __forceinline__ float prelu1(float v, float a) {
    return v > 0.f ? v : a * v;
}

// acc[8][2]: 8 rows x 2 col-pairs (4 cols). Ad: [TILE][2*K] duplicated. Ws: [K][128].
template<int K>
__device__ __forceinline__ void gemm_acc2(const float* __restrict__ Ad,
                                          const float* __restrict__ Ws,
                                          int row_base, int c0, u64t acc[8][2]) {
#pragma unroll 4
    for (int k = 0; k < K; ++k) {
        ulonglong2 w = *(const ulonglong2*)(Ws + k * LDIM + c0);
#pragma unroll
        for (int r = 0; r < 8; ++r) {
            u64t a = *(const u64t*)(Ad + ((row_base + r) * K + k) * 2);
            ffma2(acc[r][0], a, w.x);
            ffma2(acc[r][1], a, w.y);
        }
    }
}

// write prelu(acc) into Ad as duplicated [TILE][2*LDIM] layout (U buffer)
__device__ __forceinline__ void store_u_dup(float* Ad, u64t acc[8][2],
                                            int row_base, int c0, float al) {
#pragma unroll
    for (int r = 0; r < 8; ++r) {
        float2 f0 = unpack2(acc[r][0]);
        float2 f1 = unpack2(acc[r][1]);
        f0.x = prelu1(f0.x, al); f0.y = prelu1(f0.y, al);
        f1.x = prelu1(f1.x, al); f1.y = prelu1(f1.y, al);
        float* p = Ad + ((row_base + r) * LDIM + c0) * 2;
        *(float4*)(p)     = make_float4(f0.x, f0.x, f0.y, f0.y);
        *(float4*)(p + 4) = make_float4(f1.x, f1.x, f1.y, f1.y);
    }
}

__device__ __forceinline__ float4 acc_to_f4(const u64t a2[2]) {
    float2 f0 = unpack2(a2[0]);
    float2 f1 = unpack2(a2[1]);
    return make_float4(f0.x, f0.y, f1.x, f1.y);
}

// ============================ encoder (node / edge) ============================
template<int K1>
__global__ __launch_bounds__(NT, 1)
void encoder_kernel(const float* __restrict__ in,
                    const float* __restrict__ w1, const float* __restrict__ b1,
                    const float* __restrict__ aslope,
                    const float* __restrict__ w2, const float* __restrict__ b2,
                    float* __restrict__ out, int nrows) {
    extern __shared__ float sm[];
    float* Ws = sm;                        // [<=128][128]
    float* Ad = sm + LDIM * LDIM;          // duplicated A / U, up to 64x(2*128)
    int tid = threadIdx.x;
    int ty = tid >> 5, tx = tid & 31;
    int row_base = ty * 8, c0 = tx * 4;
    int r0 = blockIdx.x * TILE;

    // input tile (dup layout, row stride 2*K1)
    for (int i = tid; i < TILE * K1; i += NT) {
        int r = i / K1, k = i - r * K1;
        int gr = r0 + r; if (gr >= nrows) gr = nrows - 1;
        float v = in[(size_t)gr * K1 + k];
        Ad[2 * i] = v; Ad[2 * i + 1] = v;
    }
    cp_f4(Ws, w1, K1 * LDIM, tid);
    __syncthreads();

    float4 b1v = *(const float4*)(b1 + c0);
    u64t acc[8][2];
#pragma unroll
    for (int r = 0; r < 8; ++r) {
        acc[r][0] = pack2(b1v.x, b1v.y);
        acc[r][1] = pack2(b1v.z, b1v.w);
    }
    gemm_acc2<K1>(Ad, Ws, row_base, c0, acc);

    float al = *aslope;
    __syncthreads();                 // all done reading Ad(in) + Ws(w1)
    store_u_dup(Ad, acc, row_base, c0, al);
    cp_f4(Ws, w2, LDIM * LDIM, tid);
    __syncthreads();

    float4 b2v = *(const float4*)(b2 + c0);
#pragma unroll
    for (int r = 0; r < 8; ++r) {
        acc[r][0] = pack2(b2v.x, b2v.y);
        acc[r][1] = pack2(b2v.z, b2v.w);
    }
    gemm_acc2<LDIM>(Ad, Ws, row_base, c0, acc);

#pragma unroll
    for (int r = 0; r < 8; ++r) {
        int gr = r0 + row_base + r;
        if (gr < nrows) *(float4*)(out + (size_t)gr * LDIM + c0) = acc_to_f4(acc[r]);
    }
}

// ============================ per-layer: P/Q + zero agg ============================
__global__ __launch_bounds__(NT, 1)
void pq_kernel(const float* __restrict__ wl /* le_w1 layer base [384,128] */) {
    extern __shared__ float sm[];
    float* Ws = sm;
    float* Ad = sm + LDIM * LDIM;
    int tid = threadIdx.x;
    int ty = tid >> 5, tx = tid & 31;
    int row_base = ty * 8, c0 = tx * 4;
    int r0 = blockIdx.x * TILE;

    load_tile_rows_dup(Ad, g_h, r0, NN, tid);
    cp_f4(Ws, wl, LDIM * LDIM, tid);          // W1a (dst side)
    __syncthreads();

    float4 z = make_float4(0.f, 0.f, 0.f, 0.f);
    u64t acc[8][2];
#pragma unroll
    for (int r = 0; r < 8; ++r) { acc[r][0] = 0ull; acc[r][1] = 0ull; }
    gemm_acc2<LDIM>(Ad, Ws, row_base, c0, acc);
#pragma unroll
    for (int r = 0; r < 8; ++r) {
        int gr = r0 + row_base + r;
        if (gr < NN) {
            *(float4*)(g_P + (size_t)gr * LDIM + c0) = acc_to_f4(acc[r]);
            *(float4*)(g_agg + (size_t)gr * LDIM + c0) = z;   // zero agg for this layer
        }
    }
    __syncthreads();
    cp_f4(Ws, wl + LDIM * LDIM, LDIM * LDIM, tid);  // W1b (src side)
    __syncthreads();
#pragma unroll
    for (int r = 0; r < 8; ++r) { acc[r][0] = 0ull; acc[r][1] = 0ull; }
    gemm_acc2<LDIM>(Ad, Ws, row_base, c0, acc);
#pragma unroll
    for (int r = 0; r < 8; ++r) {
        int gr = r0 + row_base + r;
        if (gr < NN) *(float4*)(g_Q + (size_t)gr * LDIM + c0) = acc_to_f4(acc[r]);
    }
}

// ============================ per-layer: edge messages + scatter ============================
__global__ __launch_bounds__(NT, 1)
void edge_kernel(const int* __restrict__ eidx,
                 const float* __restrict__ wl,    // le_w1 layer base [384,128]
                 const float* __restrict__ b1, const float* __restrict__ aslope,
                 const float* __restrict__ w2, const float* __restrict__ b2) {
    extern __shared__ float sm[];
    float* Ws = sm;
    float* Ad = sm + LDIM * LDIM;
    int* sdst = (int*)(Ad + TILE * LDIM * 2);
    int* ssrc = sdst + TILE;
    int tid = threadIdx.x;
    int ty = tid >> 5, tx = tid & 31;
    int row_base = ty * 8, c0 = tx * 4;
    size_t e0 = (size_t)blockIdx.x * TILE;

    cp_dup(Ad, g_e + e0 * LDIM, TILE * LDIM, tid);     // e tile (dup layout)
    cp_f4(Ws, wl + 256 * LDIM, LDIM * LDIM, tid);      // W1c (e side)
    if (tid < TILE) {
        ssrc[tid] = eidx[e0 + tid];        // edge_index[0] = src (x_j)
        sdst[tid] = eidx[NE + e0 + tid];   // edge_index[1] = dst (x_i / agg index)
    }
    __syncthreads();

    float4 b1v = *(const float4*)(b1 + c0);
    u64t acc[8][2];
#pragma unroll
    for (int r = 0; r < 8; ++r) {
        int d = sdst[row_base + r];
        int s = ssrc[row_base + r];
        float4 pv = *(const float4*)(g_P + (size_t)d * LDIM + c0);
        float4 qv = *(const float4*)(g_Q + (size_t)s * LDIM + c0);
        acc[r][0] = pack2(b1v.x + pv.x + qv.x, b1v.y + pv.y + qv.y);
        acc[r][1] = pack2(b1v.z + pv.z + qv.z, b1v.w + pv.w + qv.w);
    }
    gemm_acc2<LDIM>(Ad, Ws, row_base, c0, acc);

    float al = *aslope;
    __syncthreads();              // all threads done reading e tile + W1c
    store_u_dup(Ad, acc, row_base, c0, al);
    cp_f4(Ws, w2, LDIM * LDIM, tid);
    __syncthreads();

    float4 b2v = *(const float4*)(b2 + c0);
#pragma unroll
    for (int r = 0; r < 8; ++r) {
        acc[r][0] = pack2(b2v.x, b2v.y);
        acc[r][1] = pack2(b2v.z, b2v.w);
    }
    gemm_acc2<LDIM>(Ad, Ws, row_base, c0, acc);

    // scatter-add m into agg[dst] (m never materialized)
#pragma unroll
    for (int r = 0; r < 8; ++r) {
        int d = sdst[row_base + r];
        red_add_v4(g_agg + (size_t)d * LDIM + c0, acc_to_f4(acc[r]));
    }
}

// ============================ per-layer: node update ============================
__global__ __launch_bounds__(NT, 1)
void node_kernel(const float* __restrict__ wn1,  // ln_w1 layer base [256,128]
                 const float* __restrict__ b1, const float* __restrict__ aslope,
                 const float* __restrict__ w2, const float* __restrict__ b2) {
    extern __shared__ float sm[];
    float* Ws = sm;
    float* Ad = sm + LDIM * LDIM;
    int tid = threadIdx.x;
    int ty = tid >> 5, tx = tid & 31;
    int row_base = ty * 8, c0 = tx * 4;
    int r0 = blockIdx.x * TILE;

    load_tile_rows_dup(Ad, g_h, r0, NN, tid);
    cp_f4(Ws, wn1, LDIM * LDIM, tid);          // rows 0..127 (h side)
    __syncthreads();

    float4 b1v = *(const float4*)(b1 + c0);
    u64t acc[8][2];
#pragma unroll
    for (int r = 0; r < 8; ++r) {
        acc[r][0] = pack2(b1v.x, b1v.y);
        acc[r][1] = pack2(b1v.z, b1v.w);
    }
    gemm_acc2<LDIM>(Ad, Ws, row_base, c0, acc);

    __syncthreads();
    load_tile_rows_dup(Ad, g_agg, r0, NN, tid);
    cp_f4(Ws, wn1 + LDIM * LDIM, LDIM * LDIM, tid);   // rows 128..255 (agg side)
    __syncthreads();
    gemm_acc2<LDIM>(Ad, Ws, row_base, c0, acc);       // accumulate

    float al = *aslope;
    __syncthreads();
    store_u_dup(Ad, acc, row_base, c0, al);
    cp_f4(Ws, w2, LDIM * LDIM, tid);
    __syncthreads();

    float4 b2v = *(const float4*)(b2 + c0);
#pragma unroll
    for (int r = 0; r < 8; ++r) {
        acc[r][0] = pack2(b2v.x, b2v.y);
        acc[r][1] = pack2(b2v.z, b2v.w);
    }
    gemm_acc2<LDIM>(Ad, Ws, row_base, c0, acc);

#pragma unroll
    for (int r = 0; r < 8; ++r) {
        int gr = r0 + row_base + r;
        if (gr < NN) {
            float4 hv = *(const float4*)(g_h + (size_t)gr * LDIM + c0);
            float4 u = acc_to_f4(acc[r]);
            hv.x += u.x; hv.y += u.y; hv.z += u.z; hv.w += u.w;
            *(float4*)(g_h + (size_t)gr * LDIM + c0) = hv;      // h = h + upd
        }
    }
}

// ============================ decoder ============================
__global__ __launch_bounds__(NT, 1)
void dec_kernel(const float* __restrict__ w1, const float* __restrict__ b1,
                const float* __restrict__ aslope,
                const float* __restrict__ w2, const float* __restrict__ b2,
                float* __restrict__ out) {
    extern __shared__ float sm[];
    float* Ws = sm;
    float* Ad = sm + LDIM * LDIM;
    int tid = threadIdx.x;
    int ty = tid >> 5, tx = tid & 31;
    int row_base = ty * 8, c0 = tx * 4;
    int r0 = blockIdx.x * TILE;

    load_tile_rows_dup(Ad, g_h, r0, NN, tid);
    cp_f4(Ws, w1, LDIM * LDIM, tid);
    __syncthreads();

    float4 b1v = *(const float4*)(b1 + c0);
    u64t acc[8][2];
#pragma unroll
    for (int r = 0; r < 8; ++r) {
        acc[r][0] = pack2(b1v.x, b1v.y);
        acc[r][1] = pack2(b1v.z, b1v.w);
    }
    gemm_acc2<LDIM>(Ad, Ws, row_base, c0, acc);

    float al = *aslope;
    __syncthreads();
    store_u_dup(Ad, acc, row_base, c0, al);
    __syncthreads();

    if (tid < TILE * 3) {
        int r = tid / 3, c = tid - r * 3;
        int gr = r0 + r;
        if (gr < NN) {
            float s = b2[c];
#pragma unroll 8
            for (int k = 0; k < LDIM; ++k)
                s = fmaf(Ad[(r * LDIM + k) * 2], w2[k * 3 + c], s);
            out[(size_t)gr * 3 + c] = s;
        }
    }
}

// ============================ host ============================
extern "C" void kernel_launch(void* const* d_in, const int* in_sizes, int n_in,
                              void* d_out, int out_size) {
    const float* x          = (const float*)d_in[0];
    const float* edge_attr  = (const float*)d_in[1];
    const int*   edge_index = (const int*)  d_in[2];
    const float* ne_w1 = (const float*)d_in[3];
    const float* ne_b1 = (const float*)d_in[4];
    const float* ne_a  = (const float*)d_in[5];
    const float* ne_w2 = (const float*)d_in[6];
    const float* ne_b2 = (const float*)d_in[7];
    const float* ee_w1 = (const float*)d_in[8];
    const float* ee_b1 = (const float*)d_in[9];
    const float* ee_a  = (const float*)d_in[10];
    const float* ee_w2 = (const float*)d_in[11];
    const float* ee_b2 = (const float*)d_in[12];
    const float* le_w1 = (const float*)d_in[13];
    const float* le_b1 = (const float*)d_in[14];
    const float* le_a  = (const float*)d_in[15];
    const float* le_w2 = (const float*)d_in[16];
    const float* le_b2 = (const float*)d_in[17];
    const float* ln_w1 = (const float*)d_in[18];
    const float* ln_b1 = (const float*)d_in[19];
    const float* ln_a  = (const float*)d_in[20];
    const float* ln_w2 = (const float*)d_in[21];
    const float* ln_b2 = (const float*)d_in[22];
    const float* de_w1 = (const float*)d_in[23];
    const float* de_b1 = (const float*)d_in[24];
    const float* de_a  = (const float*)d_in[25];
    const float* de_w2 = (const float*)d_in[26];
    const float* de_b2 = (const float*)d_in[27];
    float* out = (float*)d_out;

    float *p_h = nullptr, *p_e = nullptr;
    cudaGetSymbolAddress((void**)&p_h, g_h);
    cudaGetSymbolAddress((void**)&p_e, g_e);

    const int SMEM_GEMM = (LDIM * LDIM + TILE * LDIM * 2) * 4;   // 128 KB
    const int SMEM_EDGE = SMEM_GEMM + 2 * TILE * 4;              // + index staging

    cudaFuncSetAttribute(encoder_kernel<30>, cudaFuncAttributeMaxDynamicSharedMemorySize, SMEM_GEMM);
    cudaFuncSetAttribute(encoder_kernel<4>,  cudaFuncAttributeMaxDynamicSharedMemorySize, SMEM_GEMM);
    cudaFuncSetAttribute(pq_kernel,   cudaFuncAttributeMaxDynamicSharedMemorySize, SMEM_GEMM);
    cudaFuncSetAttribute(edge_kernel, cudaFuncAttributeMaxDynamicSharedMemorySize, SMEM_EDGE);
    cudaFuncSetAttribute(node_kernel, cudaFuncAttributeMaxDynamicSharedMemorySize, SMEM_GEMM);
    cudaFuncSetAttribute(dec_kernel,  cudaFuncAttributeMaxDynamicSharedMemorySize, SMEM_GEMM);

    const int nb_n = (NN + TILE - 1) / TILE;   // 313
    const int nb_e = NE / TILE;                // 5000

    encoder_kernel<30><<<nb_n, NT, SMEM_GEMM>>>(x, ne_w1, ne_b1, ne_a, ne_w2, ne_b2, p_h, NN);
    encoder_kernel<4> <<<nb_e, NT, SMEM_GEMM>>>(edge_attr, ee_w1, ee_b1, ee_a, ee_w2, ee_b2, p_e, NE);

    for (int l = 0; l < NLAYERS; ++l) {
        const float* wl = le_w1 + (size_t)l * 384 * LDIM;
        pq_kernel<<<nb_n, NT, SMEM_GEMM>>>(wl);
        edge_kernel<<<nb_e, NT, SMEM_EDGE>>>(edge_index, wl,
                                             le_b1 + l * LDIM, le_a + l,
                                             le_w2 + (size_t)l * LDIM * LDIM,
                                             le_b2 + l * LDIM);
        node_kernel<<<nb_n, NT, SMEM_GEMM>>>(ln_w1 + (size_t)l * 256 * LDIM,
                                             ln_b1 + l * LDIM, ln_a + l,
                                             ln_w2 + (size_t)l * LDIM * LDIM,
                                             ln_b2 + l * LDIM);
    }
    dec_kernel<<<nb_n, NT, SMEM_GEMM>>>(de_w1, de_b1, de_a, de_w2, de_b2, out);
}

// round 3
// speedup vs baseline: 1.4690x; 1.4690x over previous
#include <cuda_runtime.h>

#define NN 20000
#define NE 320000
#define LDIM 128
#define TILE 64
#define NT 128
#define NLAYERS 5

// -------- scratch (static device allocations; no runtime alloc) --------
__device__ float g_h[NN * LDIM];     // node features
__device__ float g_P[NN * LDIM];     // h @ W1a  (dst-side precontraction)
__device__ float g_Q[NN * LDIM];     // h @ W1b  (src-side precontraction)
__device__ float g_agg[NN * LDIM];   // segment sum accumulator
__device__ float g_e[NE * LDIM];     // encoded edge features (constant over layers)

typedef unsigned long long u64t;

// -------- packed fp32x2 primitives --------
__device__ __forceinline__ void ffma2(u64t& d, u64t a, u64t b) {
    asm("fma.rn.f32x2 %0, %1, %2, %0;" : "+l"(d) : "l"(a), "l"(b));
}
__device__ __forceinline__ u64t pack2(float x, float y) {
    u64t v; asm("mov.b64 %0, {%1, %2};" : "=l"(v) : "f"(x), "f"(y)); return v;
}
__device__ __forceinline__ float2 unpack2(u64t v) {
    float2 f; asm("mov.b64 {%0, %1}, %2;" : "=f"(f.x), "=f"(f.y) : "l"(v)); return f;
}

__device__ __forceinline__ float prelu1(float v, float a) { return v > 0.f ? v : a * v; }

__device__ __forceinline__ void red_add_v4(float* addr, float4 v) {
    asm volatile("red.global.add.v4.f32 [%0], {%1,%2,%3,%4};"
                 :: "l"(addr), "f"(v.x), "f"(v.y), "f"(v.z), "f"(v.w)
                 : "memory");
}

// -------- smem copies --------
__device__ __forceinline__ void cp_f4(float* dst, const float* __restrict__ src,
                                      int n, int tid) {
    for (int i = tid * 4; i < n; i += NT * 4)
        *(float4*)(dst + i) = *(const float4*)(src + i);
}

// transposed + XOR-swizzled A tile: element (k, r) lives at At[k*64 + (r ^ ((k&7)*4))]
// fill from a [nrows,128] row-major matrix (rows clamped)
__device__ __forceinline__ void fill_At(float* At, const float* __restrict__ src,
                                        int r0, int nrows, int tid) {
    for (int i = tid * 4; i < TILE * LDIM; i += NT * 4) {
        int r = i >> 7;
        int k = i & (LDIM - 1);          // multiple of 4
        int gr = r0 + r; if (gr >= nrows) gr = nrows - 1;
        float4 v = *(const float4*)(src + (size_t)gr * LDIM + k);
        int kx = (k & 7) * 4;            // k%4==0 -> k&7 in {0,4}
        At[(k + 0) * TILE + (r ^ (kx + 0))]  = v.x;
        At[(k + 1) * TILE + (r ^ (kx + 4))]  = v.y;
        At[(k + 2) * TILE + (r ^ (kx + 8))]  = v.z;
        At[(k + 3) * TILE + (r ^ (kx + 12))] = v.w;
    }
}

// generic scalar fill for small K1 (encoders)
__device__ __forceinline__ void fill_At_k(float* At, const float* __restrict__ src,
                                          int K1, int r0, int nrows, int tid) {
    for (int i = tid; i < TILE * K1; i += NT) {
        int r = i / K1, k = i - r * K1;
        int gr = r0 + r; if (gr >= nrows) gr = nrows - 1;
        At[k * TILE + (r ^ ((k & 7) * 4))] = src[(size_t)gr * K1 + k];
    }
}

// -------- core packed GEMM: acc[8 pairs][4 cols], rows = wy*16 .. +15 --------
template<int K>
__device__ __forceinline__ void gemm_pair(const float* __restrict__ At,
                                          const float* __restrict__ Ws,
                                          int pbw /* = wy*16 */, int c0,
                                          u64t acc[8][4]) {
#pragma unroll 4
    for (int k = 0; k < K; ++k) {
        const float* arow = At + k * TILE;
        int kx = (k & 7) * 4;
        ulonglong2 a01 = *(const ulonglong2*)(arow + ((pbw + 0)  ^ kx));
        ulonglong2 a23 = *(const ulonglong2*)(arow + ((pbw + 4)  ^ kx));
        ulonglong2 a45 = *(const ulonglong2*)(arow + ((pbw + 8)  ^ kx));
        ulonglong2 a67 = *(const ulonglong2*)(arow + ((pbw + 12) ^ kx));
        float4 w = *(const float4*)(Ws + k * LDIM + c0);
        u64t w0 = pack2(w.x, w.x), w1 = pack2(w.y, w.y);
        u64t w2 = pack2(w.z, w.z), w3 = pack2(w.w, w.w);
        ffma2(acc[0][0], a01.x, w0); ffma2(acc[0][1], a01.x, w1);
        ffma2(acc[0][2], a01.x, w2); ffma2(acc[0][3], a01.x, w3);
        ffma2(acc[1][0], a01.y, w0); ffma2(acc[1][1], a01.y, w1);
        ffma2(acc[1][2], a01.y, w2); ffma2(acc[1][3], a01.y, w3);
        ffma2(acc[2][0], a23.x, w0); ffma2(acc[2][1], a23.x, w1);
        ffma2(acc[2][2], a23.x, w2); ffma2(acc[2][3], a23.x, w3);
        ffma2(acc[3][0], a23.y, w0); ffma2(acc[3][1], a23.y, w1);
        ffma2(acc[3][2], a23.y, w2); ffma2(acc[3][3], a23.y, w3);
        ffma2(acc[4][0], a45.x, w0); ffma2(acc[4][1], a45.x, w1);
        ffma2(acc[4][2], a45.x, w2); ffma2(acc[4][3], a45.x, w3);
        ffma2(acc[5][0], a45.y, w0); ffma2(acc[5][1], a45.y, w1);
        ffma2(acc[5][2], a45.y, w2); ffma2(acc[5][3], a45.y, w3);
        ffma2(acc[6][0], a67.x, w0); ffma2(acc[6][1], a67.x, w1);
        ffma2(acc[6][2], a67.x, w2); ffma2(acc[6][3], a67.x, w3);
        ffma2(acc[7][0], a67.y, w0); ffma2(acc[7][1], a67.y, w1);
        ffma2(acc[7][2], a67.y, w2); ffma2(acc[7][3], a67.y, w3);
    }
}

__device__ __forceinline__ void acc_init(u64t acc[8][4], float4 b) {
    u64t b0 = pack2(b.x, b.x), b1 = pack2(b.y, b.y);
    u64t b2 = pack2(b.z, b.z), b3 = pack2(b.w, b.w);
#pragma unroll
    for (int p = 0; p < 8; ++p) { acc[p][0] = b0; acc[p][1] = b1; acc[p][2] = b2; acc[p][3] = b3; }
}

// prelu(acc) -> Ut (same swizzled layout as At; element (c, r) at Ut[c*64 + (r^((c&7)*4))])
__device__ __forceinline__ void store_U(float* Ut, u64t acc[8][4],
                                        int row_base, int c0, float al) {
#pragma unroll
    for (int j = 0; j < 4; ++j) {
        int c = c0 + j;
        int cx = (c & 7) * 4;
        float* col = Ut + c * TILE;
#pragma unroll
        for (int p = 0; p < 8; ++p) {
            float2 f = unpack2(acc[p][j]);
            f.x = prelu1(f.x, al);
            f.y = prelu1(f.y, al);
            int r = row_base + 2 * p;             // even
            *(float2*)(col + (r ^ cx)) = f;       // covers rows r, r+1
        }
    }
}

// assemble row vectors from pair accumulators
__device__ __forceinline__ void acc_rows(const u64t a[4], float4& lo, float4& hi) {
    float2 f0 = unpack2(a[0]), f1 = unpack2(a[1]), f2 = unpack2(a[2]), f3 = unpack2(a[3]);
    lo = make_float4(f0.x, f1.x, f2.x, f3.x);
    hi = make_float4(f0.y, f1.y, f2.y, f3.y);
}

// ============================ encoder (node / edge) ============================
template<int K1>
__global__ __launch_bounds__(NT, 2)
void encoder_kernel(const float* __restrict__ in,
                    const float* __restrict__ w1, const float* __restrict__ b1,
                    const float* __restrict__ aslope,
                    const float* __restrict__ w2, const float* __restrict__ b2,
                    float* __restrict__ out, int nrows) {
    extern __shared__ float sm[];
    float* Ws = sm;                      // [128][128]
    float* At = sm + LDIM * LDIM;        // [128][64] swizzled (also Ut)
    int tid = threadIdx.x;
    int wy = tid >> 5, tx = tid & 31;
    int row_base = wy * 16, c0 = tx * 4;
    int r0 = blockIdx.x * TILE;

    fill_At_k(At, in, K1, r0, nrows, tid);
    cp_f4(Ws, w1, K1 * LDIM, tid);
    __syncthreads();

    u64t acc[8][4];
    acc_init(acc, *(const float4*)(b1 + c0));
    gemm_pair<K1>(At, Ws, row_base, c0, acc);

    float al = *aslope;
    __syncthreads();
    store_U(At, acc, row_base, c0, al);
    cp_f4(Ws, w2, LDIM * LDIM, tid);
    __syncthreads();

    acc_init(acc, *(const float4*)(b2 + c0));
    gemm_pair<LDIM>(At, Ws, row_base, c0, acc);

#pragma unroll
    for (int p = 0; p < 8; ++p) {
        int r = row_base + 2 * p;
        float4 lo, hi; acc_rows(acc[p], lo, hi);
        int g0 = r0 + r;
        if (g0 < nrows)     *(float4*)(out + (size_t)g0 * LDIM + c0) = lo;
        if (g0 + 1 < nrows) *(float4*)(out + (size_t)(g0 + 1) * LDIM + c0) = hi;
    }
}

// ============================ per-layer: P/Q + zero agg ============================
__global__ __launch_bounds__(NT, 2)
void pq_kernel(const float* __restrict__ wl /* le_w1 layer base [384,128] */) {
    extern __shared__ float sm[];
    float* Ws = sm;
    float* At = sm + LDIM * LDIM;
    int tid = threadIdx.x;
    int wy = tid >> 5, tx = tid & 31;
    int row_base = wy * 16, c0 = tx * 4;
    int r0 = blockIdx.x * TILE;

    fill_At(At, g_h, r0, NN, tid);
    cp_f4(Ws, wl, LDIM * LDIM, tid);                 // W1a (dst side)
    __syncthreads();

    float4 z = make_float4(0.f, 0.f, 0.f, 0.f);
    u64t acc[8][4];
    acc_init(acc, z);
    gemm_pair<LDIM>(At, Ws, row_base, c0, acc);
#pragma unroll
    for (int p = 0; p < 8; ++p) {
        int g0 = r0 + row_base + 2 * p;
        float4 lo, hi; acc_rows(acc[p], lo, hi);
        if (g0 < NN) {
            *(float4*)(g_P + (size_t)g0 * LDIM + c0) = lo;
            *(float4*)(g_agg + (size_t)g0 * LDIM + c0) = z;
        }
        if (g0 + 1 < NN) {
            *(float4*)(g_P + (size_t)(g0 + 1) * LDIM + c0) = hi;
            *(float4*)(g_agg + (size_t)(g0 + 1) * LDIM + c0) = z;
        }
    }
    __syncthreads();
    cp_f4(Ws, wl + LDIM * LDIM, LDIM * LDIM, tid);   // W1b (src side)
    __syncthreads();
    acc_init(acc, z);
    gemm_pair<LDIM>(At, Ws, row_base, c0, acc);
#pragma unroll
    for (int p = 0; p < 8; ++p) {
        int g0 = r0 + row_base + 2 * p;
        float4 lo, hi; acc_rows(acc[p], lo, hi);
        if (g0 < NN)     *(float4*)(g_Q + (size_t)g0 * LDIM + c0) = lo;
        if (g0 + 1 < NN) *(float4*)(g_Q + (size_t)(g0 + 1) * LDIM + c0) = hi;
    }
}

// ============================ per-layer: edge messages + scatter ============================
__global__ __launch_bounds__(NT, 2)
void edge_kernel(const int* __restrict__ eidx,
                 const float* __restrict__ wl,    // le_w1 layer base [384,128]
                 const float* __restrict__ b1, const float* __restrict__ aslope,
                 const float* __restrict__ w2, const float* __restrict__ b2) {
    extern __shared__ float sm[];
    float* Ws = sm;
    float* At = sm + LDIM * LDIM;
    int* sdst = (int*)(At + LDIM * TILE);
    int* ssrc = sdst + TILE;
    int tid = threadIdx.x;
    int wy = tid >> 5, tx = tid & 31;
    int row_base = wy * 16, c0 = tx * 4;
    size_t e0 = (size_t)blockIdx.x * TILE;

    fill_At(At, g_e + e0 * LDIM, 0, TILE, tid);      // contiguous e tile
    cp_f4(Ws, wl + 256 * LDIM, LDIM * LDIM, tid);    // W1c (e side)
    if (tid < TILE) {
        ssrc[tid] = eidx[e0 + tid];        // edge_index[0] = src (x_j)
        sdst[tid] = eidx[NE + e0 + tid];   // edge_index[1] = dst (x_i / agg idx)
    }
    __syncthreads();

    float4 b1v = *(const float4*)(b1 + c0);
    u64t acc[8][4];
#pragma unroll
    for (int p = 0; p < 8; ++p) {
        int r = row_base + 2 * p;
        int d0 = sdst[r], d1 = sdst[r + 1];
        int s0 = ssrc[r], s1 = ssrc[r + 1];
        float4 P0 = *(const float4*)(g_P + (size_t)d0 * LDIM + c0);
        float4 P1 = *(const float4*)(g_P + (size_t)d1 * LDIM + c0);
        float4 Q0 = *(const float4*)(g_Q + (size_t)s0 * LDIM + c0);
        float4 Q1 = *(const float4*)(g_Q + (size_t)s1 * LDIM + c0);
        acc[p][0] = pack2(b1v.x + P0.x + Q0.x, b1v.x + P1.x + Q1.x);
        acc[p][1] = pack2(b1v.y + P0.y + Q0.y, b1v.y + P1.y + Q1.y);
        acc[p][2] = pack2(b1v.z + P0.z + Q0.z, b1v.z + P1.z + Q1.z);
        acc[p][3] = pack2(b1v.w + P0.w + Q0.w, b1v.w + P1.w + Q1.w);
    }
    gemm_pair<LDIM>(At, Ws, row_base, c0, acc);

    float al = *aslope;
    __syncthreads();
    store_U(At, acc, row_base, c0, al);
    cp_f4(Ws, w2, LDIM * LDIM, tid);
    __syncthreads();

    acc_init(acc, *(const float4*)(b2 + c0));
    gemm_pair<LDIM>(At, Ws, row_base, c0, acc);

#pragma unroll
    for (int p = 0; p < 8; ++p) {
        int r = row_base + 2 * p;
        float4 lo, hi; acc_rows(acc[p], lo, hi);
        red_add_v4(g_agg + (size_t)sdst[r] * LDIM + c0, lo);
        red_add_v4(g_agg + (size_t)sdst[r + 1] * LDIM + c0, hi);
    }
}

// ============================ per-layer: node update ============================
__global__ __launch_bounds__(NT, 2)
void node_kernel(const float* __restrict__ wn1,  // ln_w1 layer base [256,128]
                 const float* __restrict__ b1, const float* __restrict__ aslope,
                 const float* __restrict__ w2, const float* __restrict__ b2) {
    extern __shared__ float sm[];
    float* Ws = sm;
    float* At = sm + LDIM * LDIM;
    int tid = threadIdx.x;
    int wy = tid >> 5, tx = tid & 31;
    int row_base = wy * 16, c0 = tx * 4;
    int r0 = blockIdx.x * TILE;

    fill_At(At, g_h, r0, NN, tid);
    cp_f4(Ws, wn1, LDIM * LDIM, tid);          // rows 0..127 (h side)
    __syncthreads();

    u64t acc[8][4];
    acc_init(acc, *(const float4*)(b1 + c0));
    gemm_pair<LDIM>(At, Ws, row_base, c0, acc);

    __syncthreads();
    fill_At(At, g_agg, r0, NN, tid);
    cp_f4(Ws, wn1 + LDIM * LDIM, LDIM * LDIM, tid);   // rows 128..255 (agg side)
    __syncthreads();
    gemm_pair<LDIM>(At, Ws, row_base, c0, acc);        // accumulate

    float al = *aslope;
    __syncthreads();
    store_U(At, acc, row_base, c0, al);
    cp_f4(Ws, w2, LDIM * LDIM, tid);
    __syncthreads();

    acc_init(acc, *(const float4*)(b2 + c0));
    gemm_pair<LDIM>(At, Ws, row_base, c0, acc);

#pragma unroll
    for (int p = 0; p < 8; ++p) {
        int g0 = r0 + row_base + 2 * p;
        float4 lo, hi; acc_rows(acc[p], lo, hi);
        if (g0 < NN) {
            float4 hv = *(const float4*)(g_h + (size_t)g0 * LDIM + c0);
            hv.x += lo.x; hv.y += lo.y; hv.z += lo.z; hv.w += lo.w;
            *(float4*)(g_h + (size_t)g0 * LDIM + c0) = hv;
        }
        if (g0 + 1 < NN) {
            float4 hv = *(const float4*)(g_h + (size_t)(g0 + 1) * LDIM + c0);
            hv.x += hi.x; hv.y += hi.y; hv.z += hi.z; hv.w += hi.w;
            *(float4*)(g_h + (size_t)(g0 + 1) * LDIM + c0) = hv;
        }
    }
}

// ============================ decoder ============================
__global__ __launch_bounds__(NT, 2)
void dec_kernel(const float* __restrict__ w1, const float* __restrict__ b1,
                const float* __restrict__ aslope,
                const float* __restrict__ w2, const float* __restrict__ b2,
                float* __restrict__ out) {
    extern __shared__ float sm[];
    float* Ws = sm;
    float* At = sm + LDIM * LDIM;
    int tid = threadIdx.x;
    int wy = tid >> 5, tx = tid & 31;
    int row_base = wy * 16, c0 = tx * 4;
    int r0 = blockIdx.x * TILE;

    fill_At(At, g_h, r0, NN, tid);
    cp_f4(Ws, w1, LDIM * LDIM, tid);
    __syncthreads();

    u64t acc[8][4];
    acc_init(acc, *(const float4*)(b1 + c0));
    gemm_pair<LDIM>(At, Ws, row_base, c0, acc);

    float al = *aslope;
    __syncthreads();
    store_U(At, acc, row_base, c0, al);
    __syncthreads();

    for (int idx = tid; idx < TILE * 3; idx += NT) {
        int r = idx / 3, c = idx - r * 3;
        int gr = r0 + r;
        if (gr < NN) {
            float s = b2[c];
#pragma unroll 8
            for (int k = 0; k < LDIM; ++k)
                s = fmaf(At[k * TILE + (r ^ ((k & 7) * 4))], w2[k * 3 + c], s);
            out[(size_t)gr * 3 + c] = s;
        }
    }
}

// ============================ host ============================
extern "C" void kernel_launch(void* const* d_in, const int* in_sizes, int n_in,
                              void* d_out, int out_size) {
    const float* x          = (const float*)d_in[0];
    const float* edge_attr  = (const float*)d_in[1];
    const int*   edge_index = (const int*)  d_in[2];
    const float* ne_w1 = (const float*)d_in[3];
    const float* ne_b1 = (const float*)d_in[4];
    const float* ne_a  = (const float*)d_in[5];
    const float* ne_w2 = (const float*)d_in[6];
    const float* ne_b2 = (const float*)d_in[7];
    const float* ee_w1 = (const float*)d_in[8];
    const float* ee_b1 = (const float*)d_in[9];
    const float* ee_a  = (const float*)d_in[10];
    const float* ee_w2 = (const float*)d_in[11];
    const float* ee_b2 = (const float*)d_in[12];
    const float* le_w1 = (const float*)d_in[13];
    const float* le_b1 = (const float*)d_in[14];
    const float* le_a  = (const float*)d_in[15];
    const float* le_w2 = (const float*)d_in[16];
    const float* le_b2 = (const float*)d_in[17];
    const float* ln_w1 = (const float*)d_in[18];
    const float* ln_b1 = (const float*)d_in[19];
    const float* ln_a  = (const float*)d_in[20];
    const float* ln_w2 = (const float*)d_in[21];
    const float* ln_b2 = (const float*)d_in[22];
    const float* de_w1 = (const float*)d_in[23];
    const float* de_b1 = (const float*)d_in[24];
    const float* de_a  = (const float*)d_in[25];
    const float* de_w2 = (const float*)d_in[26];
    const float* de_b2 = (const float*)d_in[27];
    float* out = (float*)d_out;

    float *p_h = nullptr, *p_e = nullptr;
    cudaGetSymbolAddress((void**)&p_h, g_h);
    cudaGetSymbolAddress((void**)&p_e, g_e);

    const int SMEM_MAIN = (LDIM * LDIM + LDIM * TILE) * 4;   // 96 KB
    const int SMEM_EDGE = SMEM_MAIN + 2 * TILE * 4;          // + index staging

    cudaFuncSetAttribute(encoder_kernel<30>, cudaFuncAttributeMaxDynamicSharedMemorySize, SMEM_MAIN);
    cudaFuncSetAttribute(encoder_kernel<4>,  cudaFuncAttributeMaxDynamicSharedMemorySize, SMEM_MAIN);
    cudaFuncSetAttribute(pq_kernel,   cudaFuncAttributeMaxDynamicSharedMemorySize, SMEM_MAIN);
    cudaFuncSetAttribute(edge_kernel, cudaFuncAttributeMaxDynamicSharedMemorySize, SMEM_EDGE);
    cudaFuncSetAttribute(node_kernel, cudaFuncAttributeMaxDynamicSharedMemorySize, SMEM_MAIN);
    cudaFuncSetAttribute(dec_kernel,  cudaFuncAttributeMaxDynamicSharedMemorySize, SMEM_MAIN);

    const int nb_n = (NN + TILE - 1) / TILE;   // 313
    const int nb_e = NE / TILE;                // 5000

    encoder_kernel<30><<<nb_n, NT, SMEM_MAIN>>>(x, ne_w1, ne_b1, ne_a, ne_w2, ne_b2, p_h, NN);
    encoder_kernel<4> <<<nb_e, NT, SMEM_MAIN>>>(edge_attr, ee_w1, ee_b1, ee_a, ee_w2, ee_b2, p_e, NE);

    for (int l = 0; l < NLAYERS; ++l) {
        const float* wl = le_w1 + (size_t)l * 384 * LDIM;
        pq_kernel<<<nb_n, NT, SMEM_MAIN>>>(wl);
        edge_kernel<<<nb_e, NT, SMEM_EDGE>>>(edge_index, wl,
                                             le_b1 + l * LDIM, le_a + l,
                                             le_w2 + (size_t)l * LDIM * LDIM,
                                             le_b2 + l * LDIM);
        node_kernel<<<nb_n, NT, SMEM_MAIN>>>(ln_w1 + (size_t)l * 256 * LDIM,
                                             ln_b1 + l * LDIM, ln_a + l,
                                             ln_w2 + (size_t)l * LDIM * LDIM,
                                             ln_b2 + l * LDIM);
    }
    dec_kernel<<<nb_n, NT, SMEM_MAIN>>>(de_w1, de_b1, de_a, de_w2, de_b2, out);
}